// round 1
// baseline (speedup 1.0000x reference)
#include <cuda_runtime.h>
#include <cuda_bf16.h>
#include <cstdint>

// Problem dims (fixed by reference)
#define NB 16
#define NS 1024
#define ND 1024
#define NR 128

// Scratch (device globals — no allocation allowed)
__device__ float g_t [NB * NS * NR];   // 8 MB  : t = batch @ proj   [b][s][r]
__device__ float g_tT[NB * NR * NS];   // 8 MB  : t transposed       [b][r][s]
__device__ float g_nrm[NB * NS];       // 64 KB : ||t||^2 per row

// ---------- f32x2 helpers (sm_103a packed fp32 FMA) ----------
__device__ __forceinline__ void fma2(unsigned long long& d,
                                     unsigned long long a,
                                     unsigned long long b) {
    asm("fma.rn.f32x2 %0, %1, %2, %0;" : "+l"(d) : "l"(a), "l"(b));
}
__device__ __forceinline__ unsigned long long splat2(float x) {
    unsigned long long r;
    asm("mov.b64 %0, {%1, %1};" : "=l"(r) : "f"(x));
    return r;
}
__device__ __forceinline__ void unpack2(unsigned long long v, float& lo, float& hi) {
    asm("mov.b64 {%0, %1}, %2;" : "=f"(lo), "=f"(hi) : "l"(v));
}

// ============================================================
// Kernel 1: t = batch @ proj.   Output tile: 64 rows x 128 cols.
// grid = (NB*NS)/64 = 256 blocks, 256 threads.
// Each thread: 4 rows x 8 cols (16 f32x2 accumulators).
// ============================================================
__global__ __launch_bounds__(256) void k_proj(const float* __restrict__ batch,
                                              const float* __restrict__ proj) {
    __shared__ __align__(16) float As[64][33];   // batch tile, padded (conflict-free bi)
    __shared__ __align__(16) float Bs[32][128];  // proj tile

    const int tid = threadIdx.x;
    const int tx = tid & 15;          // 0..15  -> column groups
    const int ty = tid >> 4;          // 0..15  -> row groups
    const int row0 = blockIdx.x * 64; // global t-row (b*S + s)

    unsigned long long acc[4][4];
#pragma unroll
    for (int i = 0; i < 4; i++)
#pragma unroll
        for (int j = 0; j < 4; j++) acc[i][j] = 0ull;

    for (int d0 = 0; d0 < ND; d0 += 32) {
        // Load As: 64x32 floats (512 float4 slots)
#pragma unroll
        for (int it = 0; it < 2; it++) {
            int slot = tid + it * 256;
            int r = slot >> 3, d4 = slot & 7;
            float4 v = *(const float4*)&batch[(size_t)(row0 + r) * ND + d0 + d4 * 4];
            As[r][d4 * 4 + 0] = v.x;
            As[r][d4 * 4 + 1] = v.y;
            As[r][d4 * 4 + 2] = v.z;
            As[r][d4 * 4 + 3] = v.w;
        }
        // Load Bs: 32x128 floats (1024 float4 slots)
#pragma unroll
        for (int it = 0; it < 4; it++) {
            int slot = tid + it * 256;
            int kk = slot >> 5, c4 = slot & 31;
            *(float4*)&Bs[kk][c4 * 4] =
                *(const float4*)&proj[(size_t)(d0 + kk) * NR + c4 * 4];
        }
        __syncthreads();

#pragma unroll 8
        for (int k = 0; k < 32; k++) {
            unsigned long long bj[4];
#pragma unroll
            for (int jj = 0; jj < 4; jj++)
                bj[jj] = *(const unsigned long long*)&Bs[k][2 * tx + 32 * jj];
#pragma unroll
            for (int ii = 0; ii < 4; ii++) {
                unsigned long long ai = splat2(As[ty + 16 * ii][k]);
#pragma unroll
                for (int jj = 0; jj < 4; jj++) fma2(acc[ii][jj], ai, bj[jj]);
            }
        }
        __syncthreads();
    }

    // Epilogue: write t (row-major). Cols 2*tx + 32*jj (+0/1) -> coalesced float2.
#pragma unroll
    for (int ii = 0; ii < 4; ii++) {
        int row = row0 + ty + 16 * ii;
#pragma unroll
        for (int jj = 0; jj < 4; jj++) {
            float lo, hi;
            unpack2(acc[ii][jj], lo, hi);
            *(float2*)&g_t[(size_t)row * NR + 2 * tx + 32 * jj] = make_float2(lo, hi);
        }
    }
}

// ============================================================
// Kernel 2: transpose t -> tT per batch. 32x32 tiles, block (32,8).
// ============================================================
__global__ void k_transpose() {
    __shared__ float tile[32][33];
    const int b = blockIdx.z;
    const int r0 = blockIdx.x * 32;   // over R=128 -> 4
    const int s0 = blockIdx.y * 32;   // over S=1024 -> 32
    const int x = threadIdx.x, y = threadIdx.y;
    const float* src = g_t + (size_t)b * NS * NR;
    float* dst = g_tT + (size_t)b * NR * NS;
#pragma unroll
    for (int j = 0; j < 32; j += 8)
        tile[y + j][x] = src[(size_t)(s0 + y + j) * NR + r0 + x];
    __syncthreads();
#pragma unroll
    for (int j = 0; j < 32; j += 8)
        dst[(size_t)(r0 + y + j) * NS + s0 + x] = tile[x][y + j];
}

// ============================================================
// Kernel 3: row norms. One warp per row of t.
// ============================================================
__global__ void k_norms() {
    const int row = blockIdx.x * 8 + (threadIdx.x >> 5);
    const int lane = threadIdx.x & 31;
    float4 a = *(const float4*)&g_t[(size_t)row * NR + lane * 4];
    float s = a.x * a.x + a.y * a.y + a.z * a.z + a.w * a.w;
#pragma unroll
    for (int off = 16; off; off >>= 1) s += __shfl_down_sync(0xffffffffu, s, off);
    if (lane == 0) g_nrm[row] = s;
}

// ============================================================
// Kernel 4: D[b][i][j] = max(n_i + n_j - 2 * <t_i, t_j>, 0)
// Output tile 64(i) x 128(j) per block. grid (8, 16, 16), 256 thr.
// Each thread: 4 rows x 8 cols as 16 f32x2 accumulators.
// k chunked by 32: Ti[64][33] (padded), Tjs[32][128] from tT (no transpose needed).
// ============================================================
__global__ __launch_bounds__(256) void k_pairwise(float* __restrict__ out) {
    __shared__ __align__(16) float Ti[64][33];
    __shared__ __align__(16) float Tjs[32][128];

    const int b = blockIdx.z;
    const int i0 = blockIdx.y * 64;
    const int j0 = blockIdx.x * 128;
    const int tid = threadIdx.x;
    const int tx = tid & 15;
    const int ty = tid >> 4;

    const float* tb  = g_t  + (size_t)b * NS * NR;
    const float* tTb = g_tT + (size_t)b * NR * NS;

    unsigned long long acc[4][4];
#pragma unroll
    for (int i = 0; i < 4; i++)
#pragma unroll
        for (int j = 0; j < 4; j++) acc[i][j] = 0ull;

    for (int r0 = 0; r0 < NR; r0 += 32) {
        // Ti: 64 rows x 32 k (512 float4 slots), padded scalar stores
#pragma unroll
        for (int it = 0; it < 2; it++) {
            int slot = tid + it * 256;
            int r = slot >> 3, k4 = slot & 7;
            float4 v = *(const float4*)&tb[(size_t)(i0 + r) * NR + r0 + k4 * 4];
            Ti[r][k4 * 4 + 0] = v.x;
            Ti[r][k4 * 4 + 1] = v.y;
            Ti[r][k4 * 4 + 2] = v.z;
            Ti[r][k4 * 4 + 3] = v.w;
        }
        // Tjs: 32 k x 128 cols straight from tT (coalesced, conflict-free)
#pragma unroll
        for (int it = 0; it < 4; it++) {
            int slot = tid + it * 256;
            int kk = slot >> 5, c4 = slot & 31;
            *(float4*)&Tjs[kk][c4 * 4] =
                *(const float4*)&tTb[(size_t)(r0 + kk) * NS + j0 + c4 * 4];
        }
        __syncthreads();

#pragma unroll 8
        for (int k = 0; k < 32; k++) {
            unsigned long long bj[4];
#pragma unroll
            for (int jj = 0; jj < 4; jj++)
                bj[jj] = *(const unsigned long long*)&Tjs[k][2 * tx + 32 * jj];
#pragma unroll
            for (int ii = 0; ii < 4; ii++) {
                unsigned long long ai = splat2(Ti[ty + 16 * ii][k]);
#pragma unroll
                for (int jj = 0; jj < 4; jj++) fma2(acc[ii][jj], ai, bj[jj]);
            }
        }
        __syncthreads();
    }

    // Epilogue: d = n_i + n_j - 2*dot, clamp at 0. Coalesced float2 stores.
    const float* nb = g_nrm + (size_t)b * NS;
#pragma unroll
    for (int ii = 0; ii < 4; ii++) {
        int i = i0 + ty + 16 * ii;
        float ni = __ldg(&nb[i]);
#pragma unroll
        for (int jj = 0; jj < 4; jj++) {
            int j = j0 + 2 * tx + 32 * jj;
            float lo, hi;
            unpack2(acc[ii][jj], lo, hi);
            float d0 = fmaxf(ni + __ldg(&nb[j])     - 2.0f * lo, 0.0f);
            float d1 = fmaxf(ni + __ldg(&nb[j + 1]) - 2.0f * hi, 0.0f);
            *(float2*)&out[(size_t)b * NS * NS + (size_t)i * NS + j] = make_float2(d0, d1);
        }
    }
}

// ============================================================
extern "C" void kernel_launch(void* const* d_in, const int* in_sizes, int n_in,
                              void* d_out, int out_size) {
    const float* batch = (const float*)d_in[0]; // [16,1024,1024]
    const float* proj  = (const float*)d_in[1]; // [1024,128]
    float* out = (float*)d_out;                 // [16,1024,1024]

    k_proj<<<(NB * NS) / 64, 256>>>(batch, proj);
    k_transpose<<<dim3(NR / 32, NS / 32, NB), dim3(32, 8)>>>();
    k_norms<<<(NB * NS) / 8, 256>>>();
    k_pairwise<<<dim3(NS / 128, NS / 64, NB), 256>>>(out);
}

// round 9
// speedup vs baseline: 3.8173x; 3.8173x over previous
#include <cuda_runtime.h>
#include <cuda_fp16.h>
#include <cstdint>

#define NB 16
#define NS 1024
#define ND 1024
#define NR 128

// ---------------- scratch (device globals; no runtime allocation) ----------------
__device__ __align__(16) __half g_t[NB * NS * NR];   // 4 MB   t-hat fp16 [row][r]
__device__ __align__(16) __half g_pT[NR * ND];       // 256 KB proj^T fp16 [n][k]
__device__ float g_nrm[NB * NS];                     // 64 KB  ||t-hat||^2

// ---------------- PTX helpers (baseline ISA only: ldmatrix + mma.sync) ----------------
__device__ __forceinline__ uint32_t smem_u32(const void* p) {
    uint32_t a;
    asm("{ .reg .u64 t; cvta.to.shared.u64 t, %1; cvt.u32.u64 %0, t; }" : "=r"(a) : "l"(p));
    return a;
}

#define LDSM4(r0, r1, r2, r3, a)                                                    \
    asm volatile("ldmatrix.sync.aligned.m8n8.x4.shared.b16 {%0,%1,%2,%3}, [%4];"    \
                 : "=r"(r0), "=r"(r1), "=r"(r2), "=r"(r3) : "r"(a))

#define MMA16816(c, a, b0, b1)                                                      \
    asm volatile("mma.sync.aligned.m16n8k16.row.col.f32.f16.f16.f32 "               \
                 "{%0,%1,%2,%3},{%4,%5,%6,%7},{%8,%9},{%0,%1,%2,%3};"               \
                 : "+f"((c)[0]), "+f"((c)[1]), "+f"((c)[2]), "+f"((c)[3])           \
                 : "r"((a)[0]), "r"((a)[1]), "r"((a)[2]), "r"((a)[3]),              \
                   "r"(b0), "r"(b1))

__device__ __forceinline__ uint32_t h2u(__half2 h) {
    return *reinterpret_cast<uint32_t*>(&h);
}

// ============================================================
// Kernel 0: proj [D][R] fp32 -> projT fp16 [n][k]
// ============================================================
__global__ void k_split_proj(const float* __restrict__ proj) {
    __shared__ float tile[32][33];
    const int k0 = blockIdx.x * 32, n0 = blockIdx.y * 32;
    const int x = threadIdx.x, y = threadIdx.y;
#pragma unroll
    for (int j = 0; j < 32; j += 8)
        tile[y + j][x] = proj[(size_t)(k0 + y + j) * NR + n0 + x];
    __syncthreads();
#pragma unroll
    for (int j = 0; j < 32; j += 8)
        g_pT[(size_t)(n0 + y + j) * ND + k0 + x] = __float2half(tile[x][y + j]);
}

// ============================================================
// Kernel 1: t = batch @ proj  (HMMA fp16, fp32 accum)
// CTA: 128 rows x 128 cols, K chunks of 64, register-prefetch overlap.
// 8 warps as 2(m) x 4(n); warp tile 64x32 = 4x4 mma tiles.
// smem rows padded: A,B stride 144 B (64 halves + 8 pad) -> conflict-free ldmatrix.
// ============================================================
__global__ __launch_bounds__(256) void k_gemm1(const float* __restrict__ batch) {
    __shared__ __align__(16) char smem[2 * 128 * 144];  // A @0 (18432), B @18432
    const int tid = threadIdx.x, wid = tid >> 5, lane = tid & 31;
    const int warp_m = wid >> 2, warp_n = wid & 3;
    const int row0 = blockIdx.x * 128;

    const uint32_t sA = smem_u32(smem);
    const uint32_t sB = sA + 128 * 144;

    float acc[4][4][4];
#pragma unroll
    for (int mi = 0; mi < 4; mi++)
#pragma unroll
        for (int nj = 0; nj < 4; nj++)
#pragma unroll
            for (int q = 0; q < 4; q++) acc[mi][nj][q] = 0.f;

    uint2 Areg[8];
    uint4 Breg[4];

    auto load_chunk = [&](int c) {
        const int k0 = c * 64;
#pragma unroll
        for (int it = 0; it < 8; it++) {
            int slot = tid + it * 256;
            int r = slot >> 4, q = slot & 15;
            float4 v = *(const float4*)&batch[(size_t)(row0 + r) * ND + k0 + q * 4];
            Areg[it] = make_uint2(h2u(__floats2half2_rn(v.x, v.y)),
                                  h2u(__floats2half2_rn(v.z, v.w)));
        }
#pragma unroll
        for (int it = 0; it < 4; it++) {
            int slot = tid + it * 256;
            int n = slot >> 3, q = slot & 7;
            Breg[it] = *(const uint4*)((const char*)g_pT + (size_t)n * 2048 + (size_t)(k0 + q * 8) * 2);
        }
    };

    load_chunk(0);

    for (int c = 0; c < 16; c++) {
        __syncthreads();  // smem free (prev compute done)
#pragma unroll
        for (int it = 0; it < 8; it++) {
            int slot = tid + it * 256;
            int r = slot >> 4, q = slot & 15;
            *(uint2*)(smem + r * 144 + q * 8) = Areg[it];
        }
#pragma unroll
        for (int it = 0; it < 4; it++) {
            int slot = tid + it * 256;
            int n = slot >> 3, q = slot & 7;
            *(uint4*)(smem + 128 * 144 + n * 144 + q * 16) = Breg[it];
        }
        __syncthreads();
        if (c < 15) load_chunk(c + 1);  // LDGs fly while we do mma below

#pragma unroll
        for (int ks = 0; ks < 4; ks++) {
            uint32_t a[4][4];
#pragma unroll
            for (int mi = 0; mi < 4; mi++) {
                uint32_t addr = sA + (warp_m * 64 + mi * 16 + (lane & 15)) * 144
                              + ks * 32 + (lane >> 4) * 16;
                LDSM4(a[mi][0], a[mi][1], a[mi][2], a[mi][3], addr);
            }
            uint32_t b[4][2];
#pragma unroll
            for (int njp = 0; njp < 2; njp++) {
                uint32_t addr = sB + (warp_n * 32 + njp * 16 + ((lane >> 4) << 3) + (lane & 7)) * 144
                              + ks * 32 + (((lane >> 3) & 1) << 4);
                LDSM4(b[2 * njp][0], b[2 * njp][1], b[2 * njp + 1][0], b[2 * njp + 1][1], addr);
            }
#pragma unroll
            for (int mi = 0; mi < 4; mi++)
#pragma unroll
                for (int nj = 0; nj < 4; nj++)
                    MMA16816(acc[mi][nj], a[mi], b[nj][0], b[nj][1]);
        }
    }

    // Epilogue: fp32 -> fp16, store t-hat
#pragma unroll
    for (int mi = 0; mi < 4; mi++) {
        int r = row0 + warp_m * 64 + mi * 16 + (lane >> 2);
#pragma unroll
        for (int nj = 0; nj < 4; nj++) {
            int col = warp_n * 32 + nj * 8 + (lane & 3) * 2;
            *(uint32_t*)&g_t[(size_t)r * NR + col] =
                h2u(__floats2half2_rn(acc[mi][nj][0], acc[mi][nj][1]));
            *(uint32_t*)&g_t[(size_t)(r + 8) * NR + col] =
                h2u(__floats2half2_rn(acc[mi][nj][2], acc[mi][nj][3]));
        }
    }
}

// ============================================================
// Kernel 2: row norms of t-hat (fp16 -> fp32 accumulate). One warp per row.
// ============================================================
__global__ void k_norms() {
    const int row = blockIdx.x * 8 + (threadIdx.x >> 5);
    const int lane = threadIdx.x & 31;
    uint2 v = *(const uint2*)((const char*)g_t + (size_t)row * 256 + lane * 8);
    __half2 h0 = *reinterpret_cast<__half2*>(&v.x);
    __half2 h1 = *reinterpret_cast<__half2*>(&v.y);
    float2 f0 = __half22float2(h0), f1 = __half22float2(h1);
    float s = f0.x * f0.x + f0.y * f0.y + f1.x * f1.x + f1.y * f1.y;
#pragma unroll
    for (int off = 16; off; off >>= 1) s += __shfl_down_sync(0xffffffffu, s, off);
    if (lane == 0) g_nrm[row] = s;
}

// ============================================================
// Kernel 3: D[b][i][j] = max(n_i + n_j - 2 <t_i, t_j>, 0)
// CTA: 128(i) x 128(j), K=128 fully in smem (no k-loop).
// smem rows padded: stride 272 B (128 halves + 8 pad).
// ============================================================
#define G2_SMEM (2 * 128 * 272)
__global__ __launch_bounds__(256) void k_gemm2(float* __restrict__ out) {
    extern __shared__ __align__(16) char smem[];
    const int tid = threadIdx.x, wid = tid >> 5, lane = tid & 31;
    const int warp_m = wid >> 2, warp_n = wid & 3;
    const int b = blockIdx.z;
    const int i0 = blockIdx.y * 128, j0 = blockIdx.x * 128;

    const uint32_t sA = smem_u32(smem);
    const uint32_t sB = sA + 128 * 272;

    // Load A (i-rows) and B (j-rows) of t-hat: 32 KB each
#pragma unroll
    for (int it = 0; it < 8; it++) {
        int slot = tid + it * 256;
        int r = slot >> 4, q = slot & 15;
        *(uint4*)(smem + r * 272 + q * 16) =
            *(const uint4*)((const char*)g_t + (size_t)(b * NS + i0 + r) * 256 + q * 16);
        *(uint4*)(smem + 128 * 272 + r * 272 + q * 16) =
            *(const uint4*)((const char*)g_t + (size_t)(b * NS + j0 + r) * 256 + q * 16);
    }
    __syncthreads();

    float acc[4][4][4];
#pragma unroll
    for (int mi = 0; mi < 4; mi++)
#pragma unroll
        for (int nj = 0; nj < 4; nj++)
#pragma unroll
            for (int q = 0; q < 4; q++) acc[mi][nj][q] = 0.f;

#pragma unroll
    for (int ks = 0; ks < 8; ks++) {
        uint32_t a[4][4];
#pragma unroll
        for (int mi = 0; mi < 4; mi++) {
            uint32_t addr = sA + (warp_m * 64 + mi * 16 + (lane & 15)) * 272
                          + ks * 32 + (lane >> 4) * 16;
            LDSM4(a[mi][0], a[mi][1], a[mi][2], a[mi][3], addr);
        }
        uint32_t bfr[4][2];
#pragma unroll
        for (int njp = 0; njp < 2; njp++) {
            uint32_t addr = sB + (warp_n * 32 + njp * 16 + ((lane >> 4) << 3) + (lane & 7)) * 272
                          + ks * 32 + (((lane >> 3) & 1) << 4);
            LDSM4(bfr[2 * njp][0], bfr[2 * njp][1], bfr[2 * njp + 1][0], bfr[2 * njp + 1][1], addr);
        }
#pragma unroll
        for (int mi = 0; mi < 4; mi++)
#pragma unroll
            for (int nj = 0; nj < 4; nj++)
                MMA16816(acc[mi][nj], a[mi], bfr[nj][0], bfr[nj][1]);
    }

    // Epilogue: d = n_i + n_j - 2*dot, clamp 0
    const float* nrm = g_nrm + (size_t)b * NS;
#pragma unroll
    for (int nj = 0; nj < 4; nj++) {
        int j = j0 + warp_n * 32 + nj * 8 + (lane & 3) * 2;
        float njn0 = __ldg(&nrm[j]), njn1 = __ldg(&nrm[j + 1]);
#pragma unroll
        for (int mi = 0; mi < 4; mi++) {
            int i = i0 + warp_m * 64 + mi * 16 + (lane >> 2);
            float ni0 = __ldg(&nrm[i]), ni1 = __ldg(&nrm[i + 8]);
            float2 o0, o1;
            o0.x = fmaxf(ni0 + njn0 - 2.f * acc[mi][nj][0], 0.f);
            o0.y = fmaxf(ni0 + njn1 - 2.f * acc[mi][nj][1], 0.f);
            o1.x = fmaxf(ni1 + njn0 - 2.f * acc[mi][nj][2], 0.f);
            o1.y = fmaxf(ni1 + njn1 - 2.f * acc[mi][nj][3], 0.f);
            *(float2*)&out[((size_t)b * NS + i) * NS + j] = o0;
            *(float2*)&out[((size_t)b * NS + i + 8) * NS + j] = o1;
        }
    }
}

// ============================================================
extern "C" void kernel_launch(void* const* d_in, const int* in_sizes, int n_in,
                              void* d_out, int out_size) {
    (void)in_sizes; (void)n_in; (void)out_size;
    const float* batch = (const float*)d_in[0];  // [16,1024,1024]
    const float* proj  = (const float*)d_in[1];  // [1024,128]
    float* out = (float*)d_out;                  // [16,1024,1024]

    cudaFuncSetAttribute(k_gemm2, cudaFuncAttributeMaxDynamicSharedMemorySize, G2_SMEM);

    k_split_proj<<<dim3(32, 4), dim3(32, 8)>>>(proj);
    k_gemm1<<<(NB * NS) / 128, 256>>>(batch);
    k_norms<<<(NB * NS) / 8, 256>>>();
    k_gemm2<<<dim3(NS / 128, NS / 128, NB), 256, G2_SMEM>>>(out);
}

// round 14
// speedup vs baseline: 4.2111x; 1.1032x over previous
#include <cuda_runtime.h>
#include <cuda_fp16.h>
#include <cstdint>

#define NB 16
#define NS 1024
#define ND 1024
#define NR 128

// ---------------- scratch (device globals; no runtime allocation) ----------------
__device__ __align__(16) __half g_t[NB * NS * NR];   // 4 MB   t-hat fp16 [row][r]
__device__ __align__(16) __half g_pT[NR * ND];       // 256 KB proj^T fp16 [n][k]
__device__ float g_nrm[NB * NS];                     // 64 KB  ||t-hat||^2

// ---------------- PTX helpers (baseline ISA only: ldmatrix + mma.sync) ----------------
__device__ __forceinline__ uint32_t smem_u32(const void* p) {
    uint32_t a;
    asm("{ .reg .u64 t; cvta.to.shared.u64 t, %1; cvt.u32.u64 %0, t; }" : "=r"(a) : "l"(p));
    return a;
}

#define LDSM4(r0, r1, r2, r3, a)                                                    \
    asm volatile("ldmatrix.sync.aligned.m8n8.x4.shared.b16 {%0,%1,%2,%3}, [%4];"    \
                 : "=r"(r0), "=r"(r1), "=r"(r2), "=r"(r3) : "r"(a))

#define MMA16816(c, a, b0, b1)                                                      \
    asm volatile("mma.sync.aligned.m16n8k16.row.col.f32.f16.f16.f32 "               \
                 "{%0,%1,%2,%3},{%4,%5,%6,%7},{%8,%9},{%0,%1,%2,%3};"               \
                 : "+f"((c)[0]), "+f"((c)[1]), "+f"((c)[2]), "+f"((c)[3])           \
                 : "r"((a)[0]), "r"((a)[1]), "r"((a)[2]), "r"((a)[3]),              \
                   "r"(b0), "r"(b1))

__device__ __forceinline__ uint32_t h2u(__half2 h) {
    return *reinterpret_cast<uint32_t*>(&h);
}

// ============================================================
// Kernel 0: proj [D][R] fp32 -> projT fp16 [n][k]
// ============================================================
__global__ void k_split_proj(const float* __restrict__ proj) {
    __shared__ float tile[32][33];
    const int k0 = blockIdx.x * 32, n0 = blockIdx.y * 32;
    const int x = threadIdx.x, y = threadIdx.y;
#pragma unroll
    for (int j = 0; j < 32; j += 8)
        tile[y + j][x] = proj[(size_t)(k0 + y + j) * NR + n0 + x];
    __syncthreads();
#pragma unroll
    for (int j = 0; j < 32; j += 8)
        g_pT[(size_t)(n0 + y + j) * ND + k0 + x] = __float2half(tile[x][y + j]);
}

// ============================================================
// Kernel 1: t = batch @ proj  (HMMA fp16, fp32 accum)  — unchanged from R9 pass
// ============================================================
__global__ __launch_bounds__(256) void k_gemm1(const float* __restrict__ batch) {
    __shared__ __align__(16) char smem[2 * 128 * 144];  // A @0, B @18432
    const int tid = threadIdx.x, wid = tid >> 5, lane = tid & 31;
    const int warp_m = wid >> 2, warp_n = wid & 3;
    const int row0 = blockIdx.x * 128;

    const uint32_t sA = smem_u32(smem);
    const uint32_t sB = sA + 128 * 144;

    float acc[4][4][4];
#pragma unroll
    for (int mi = 0; mi < 4; mi++)
#pragma unroll
        for (int nj = 0; nj < 4; nj++)
#pragma unroll
            for (int q = 0; q < 4; q++) acc[mi][nj][q] = 0.f;

    uint2 Areg[8];
    uint4 Breg[4];

    auto load_chunk = [&](int c) {
        const int k0 = c * 64;
#pragma unroll
        for (int it = 0; it < 8; it++) {
            int slot = tid + it * 256;
            int r = slot >> 4, q = slot & 15;
            float4 v = *(const float4*)&batch[(size_t)(row0 + r) * ND + k0 + q * 4];
            Areg[it] = make_uint2(h2u(__floats2half2_rn(v.x, v.y)),
                                  h2u(__floats2half2_rn(v.z, v.w)));
        }
#pragma unroll
        for (int it = 0; it < 4; it++) {
            int slot = tid + it * 256;
            int n = slot >> 3, q = slot & 7;
            Breg[it] = *(const uint4*)((const char*)g_pT + (size_t)n * 2048 + (size_t)(k0 + q * 8) * 2);
        }
    };

    load_chunk(0);

    for (int c = 0; c < 16; c++) {
        __syncthreads();
#pragma unroll
        for (int it = 0; it < 8; it++) {
            int slot = tid + it * 256;
            int r = slot >> 4, q = slot & 15;
            *(uint2*)(smem + r * 144 + q * 8) = Areg[it];
        }
#pragma unroll
        for (int it = 0; it < 4; it++) {
            int slot = tid + it * 256;
            int n = slot >> 3, q = slot & 7;
            *(uint4*)(smem + 128 * 144 + n * 144 + q * 16) = Breg[it];
        }
        __syncthreads();
        if (c < 15) load_chunk(c + 1);

#pragma unroll
        for (int ks = 0; ks < 4; ks++) {
            uint32_t a[4][4];
#pragma unroll
            for (int mi = 0; mi < 4; mi++) {
                uint32_t addr = sA + (warp_m * 64 + mi * 16 + (lane & 15)) * 144
                              + ks * 32 + (lane >> 4) * 16;
                LDSM4(a[mi][0], a[mi][1], a[mi][2], a[mi][3], addr);
            }
            uint32_t b[4][2];
#pragma unroll
            for (int njp = 0; njp < 2; njp++) {
                uint32_t addr = sB + (warp_n * 32 + njp * 16 + ((lane >> 4) << 3) + (lane & 7)) * 144
                              + ks * 32 + (((lane >> 3) & 1) << 4);
                LDSM4(b[2 * njp][0], b[2 * njp][1], b[2 * njp + 1][0], b[2 * njp + 1][1], addr);
            }
#pragma unroll
            for (int mi = 0; mi < 4; mi++)
#pragma unroll
                for (int nj = 0; nj < 4; nj++)
                    MMA16816(acc[mi][nj], a[mi], b[nj][0], b[nj][1]);
        }
    }

#pragma unroll
    for (int mi = 0; mi < 4; mi++) {
        int r = row0 + warp_m * 64 + mi * 16 + (lane >> 2);
#pragma unroll
        for (int nj = 0; nj < 4; nj++) {
            int col = warp_n * 32 + nj * 8 + (lane & 3) * 2;
            *(uint32_t*)&g_t[(size_t)r * NR + col] =
                h2u(__floats2half2_rn(acc[mi][nj][0], acc[mi][nj][1]));
            *(uint32_t*)&g_t[(size_t)(r + 8) * NR + col] =
                h2u(__floats2half2_rn(acc[mi][nj][2], acc[mi][nj][3]));
        }
    }
}

// ============================================================
// Kernel 2: row norms of t-hat. One warp per row.
// ============================================================
__global__ void k_norms() {
    const int row = blockIdx.x * 8 + (threadIdx.x >> 5);
    const int lane = threadIdx.x & 31;
    uint2 v = *(const uint2*)((const char*)g_t + (size_t)row * 256 + lane * 8);
    __half2 h0 = *reinterpret_cast<__half2*>(&v.x);
    __half2 h1 = *reinterpret_cast<__half2*>(&v.y);
    float2 f0 = __half22float2(h0), f1 = __half22float2(h1);
    float s = f0.x * f0.x + f0.y * f0.y + f1.x * f1.x + f1.y * f1.y;
#pragma unroll
    for (int off = 16; off; off >>= 1) s += __shfl_down_sync(0xffffffffu, s, off);
    if (lane == 0) g_nrm[row] = s;
}

// ============================================================
// Kernel 3: D[b][i][j] = max(n_i + n_j - 2 <t_i, t_j>, 0)
// SYMMETRIC: only block-pairs bi<=bj (36/batch). Off-diag blocks are
// mirrored via an smem fp32 transpose stage (stride 132 floats).
// K-loop uses ldmatrix fragment double-buffering.
// ============================================================
#define SMD_STRIDE 132
#define G2_SMEM (2 * 128 * 272)  // 69632 >= 128*132*4 = 67584 staging
__global__ __launch_bounds__(256) void k_gemm2(float* __restrict__ out) {
    extern __shared__ __align__(16) char smem[];
    const int tid = threadIdx.x, wid = tid >> 5, lane = tid & 31;
    const int warp_m = wid >> 2, warp_n = wid & 3;
    const int b = blockIdx.y;

    // map blockIdx.x -> (bi, bj) with bi <= bj over 8x8 blocks
    int bi = 0, rem = blockIdx.x;
    while (rem >= 8 - bi) { rem -= 8 - bi; bi++; }
    const int bj = bi + rem;
    const int i0 = bi * 128, j0 = bj * 128;

    const uint32_t sA = smem_u32(smem);
    const uint32_t sB = sA + 128 * 272;

    // Load A (i-rows) and B (j-rows) of t-hat: 32 KB each
#pragma unroll
    for (int it = 0; it < 8; it++) {
        int slot = tid + it * 256;
        int r = slot >> 4, q = slot & 15;
        *(uint4*)(smem + r * 272 + q * 16) =
            *(const uint4*)((const char*)g_t + (size_t)(b * NS + i0 + r) * 256 + q * 16);
        *(uint4*)(smem + 128 * 272 + r * 272 + q * 16) =
            *(const uint4*)((const char*)g_t + (size_t)(b * NS + j0 + r) * 256 + q * 16);
    }
    __syncthreads();

    float acc[4][4][4];
#pragma unroll
    for (int mi = 0; mi < 4; mi++)
#pragma unroll
        for (int nj = 0; nj < 4; nj++)
#pragma unroll
            for (int q = 0; q < 4; q++) acc[mi][nj][q] = 0.f;

    // fragment double-buffer
    uint32_t afr[2][4][4], bfr[2][4][2];

#define LOAD_FRAGS(ks, buf)                                                              \
    do {                                                                                 \
        _Pragma("unroll")                                                                \
        for (int mi = 0; mi < 4; mi++) {                                                 \
            uint32_t addr = sA + (warp_m * 64 + mi * 16 + (lane & 15)) * 272             \
                          + (ks) * 32 + (lane >> 4) * 16;                                \
            LDSM4(afr[buf][mi][0], afr[buf][mi][1], afr[buf][mi][2], afr[buf][mi][3], addr); \
        }                                                                                \
        _Pragma("unroll")                                                                \
        for (int njp = 0; njp < 2; njp++) {                                              \
            uint32_t addr = sB + (warp_n * 32 + njp * 16 + ((lane >> 4) << 3) + (lane & 7)) * 272 \
                          + (ks) * 32 + (((lane >> 3) & 1) << 4);                        \
            LDSM4(bfr[buf][2 * njp][0], bfr[buf][2 * njp][1],                            \
                  bfr[buf][2 * njp + 1][0], bfr[buf][2 * njp + 1][1], addr);             \
        }                                                                                \
    } while (0)

    LOAD_FRAGS(0, 0);
#pragma unroll
    for (int ks = 0; ks < 8; ks++) {
        const int cur = ks & 1;
        if (ks < 7) LOAD_FRAGS(ks + 1, cur ^ 1);
#pragma unroll
        for (int mi = 0; mi < 4; mi++)
#pragma unroll
            for (int nj = 0; nj < 4; nj++)
                MMA16816(acc[mi][nj], afr[cur][mi], bfr[cur][nj][0], bfr[cur][nj][1]);
    }
#undef LOAD_FRAGS

    // Epilogue: o = max(n_i + n_j - 2*dot, 0); write (i0,j0) block coalesced.
    const float* nrm = g_nrm + (size_t)b * NS;
    float oval[4][4][4];
#pragma unroll
    for (int nj = 0; nj < 4; nj++) {
        int j = j0 + warp_n * 32 + nj * 8 + (lane & 3) * 2;
        float njn0 = __ldg(&nrm[j]), njn1 = __ldg(&nrm[j + 1]);
#pragma unroll
        for (int mi = 0; mi < 4; mi++) {
            int i = i0 + warp_m * 64 + mi * 16 + (lane >> 2);
            float ni0 = __ldg(&nrm[i]), ni1 = __ldg(&nrm[i + 8]);
            oval[mi][nj][0] = fmaxf(ni0 + njn0 - 2.f * acc[mi][nj][0], 0.f);
            oval[mi][nj][1] = fmaxf(ni0 + njn1 - 2.f * acc[mi][nj][1], 0.f);
            oval[mi][nj][2] = fmaxf(ni1 + njn0 - 2.f * acc[mi][nj][2], 0.f);
            oval[mi][nj][3] = fmaxf(ni1 + njn1 - 2.f * acc[mi][nj][3], 0.f);
            *(float2*)&out[((size_t)b * NS + i) * NS + j] = make_float2(oval[mi][nj][0], oval[mi][nj][1]);
            *(float2*)&out[((size_t)b * NS + i + 8) * NS + j] = make_float2(oval[mi][nj][2], oval[mi][nj][3]);
        }
    }

    if (bi != bj) {
        // Mirror: stage TRANSPOSED (smD[j_local][i_local]), then coalesced rows out.
        __syncthreads();  // everyone done reading A/B tiles from smem
        float* smD = (float*)smem;
#pragma unroll
        for (int nj = 0; nj < 4; nj++) {
            int jl = warp_n * 32 + nj * 8 + (lane & 3) * 2;
#pragma unroll
            for (int mi = 0; mi < 4; mi++) {
                int il = warp_m * 64 + mi * 16 + (lane >> 2);
                smD[(size_t)jl * SMD_STRIDE + il]            = oval[mi][nj][0];
                smD[(size_t)(jl + 1) * SMD_STRIDE + il]      = oval[mi][nj][1];
                smD[(size_t)jl * SMD_STRIDE + il + 8]        = oval[mi][nj][2];
                smD[(size_t)(jl + 1) * SMD_STRIDE + il + 8]  = oval[mi][nj][3];
            }
        }
        __syncthreads();
        // write (j0, i0) block: row j0+jr, cols i0..i0+127
#pragma unroll
        for (int it = 0; it < 16; it++) {
            int slot = tid + it * 256;          // 4096 slots
            int cg = slot & 31, jr = slot >> 5; // lane-consecutive col groups
            float4 v = *(const float4*)&smD[(size_t)jr * SMD_STRIDE + cg * 4];
            *(float4*)&out[((size_t)b * NS + j0 + jr) * NS + i0 + cg * 4] = v;
        }
    }
}

// ============================================================
extern "C" void kernel_launch(void* const* d_in, const int* in_sizes, int n_in,
                              void* d_out, int out_size) {
    (void)in_sizes; (void)n_in; (void)out_size;
    const float* batch = (const float*)d_in[0];  // [16,1024,1024]
    const float* proj  = (const float*)d_in[1];  // [1024,128]
    float* out = (float*)d_out;                  // [16,1024,1024]

    cudaFuncSetAttribute(k_gemm2, cudaFuncAttributeMaxDynamicSharedMemorySize, G2_SMEM);

    k_split_proj<<<dim3(32, 4), dim3(32, 8)>>>(proj);
    k_gemm1<<<(NB * NS) / 128, 256>>>(batch);
    k_norms<<<(NB * NS) / 8, 256>>>();
    k_gemm2<<<dim3(36, NB), 256, G2_SMEM>>>(out);
}

// round 17
// speedup vs baseline: 4.4364x; 1.0535x over previous
#include <cuda_runtime.h>
#include <cuda_fp16.h>
#include <cstdint>

#define NB 16
#define NS 1024
#define ND 1024
#define NR 128

// ---------------- scratch (device globals; no runtime allocation) ----------------
__device__ __align__(16) __half g_t[NB * NS * NR];   // 4 MB   t-hat fp16 [row][r]
__device__ __align__(16) __half g_pT[NR * ND];       // 256 KB proj^T fp16 [n][k]
__device__ float g_nrm[NB * NS];                     // 64 KB  ||t-hat||^2

// ---------------- PTX helpers (baseline ISA only: ldmatrix + mma.sync) ----------------
__device__ __forceinline__ uint32_t smem_u32(const void* p) {
    uint32_t a;
    asm("{ .reg .u64 t; cvta.to.shared.u64 t, %1; cvt.u32.u64 %0, t; }" : "=r"(a) : "l"(p));
    return a;
}

#define LDSM4(r0, r1, r2, r3, a)                                                    \
    asm volatile("ldmatrix.sync.aligned.m8n8.x4.shared.b16 {%0,%1,%2,%3}, [%4];"    \
                 : "=r"(r0), "=r"(r1), "=r"(r2), "=r"(r3) : "r"(a))

#define MMA16816(c, a, b0, b1)                                                      \
    asm volatile("mma.sync.aligned.m16n8k16.row.col.f32.f16.f16.f32 "               \
                 "{%0,%1,%2,%3},{%4,%5,%6,%7},{%8,%9},{%0,%1,%2,%3};"               \
                 : "+f"((c)[0]), "+f"((c)[1]), "+f"((c)[2]), "+f"((c)[3])           \
                 : "r"((a)[0]), "r"((a)[1]), "r"((a)[2]), "r"((a)[3]),              \
                   "r"(b0), "r"(b1))

__device__ __forceinline__ uint32_t h2u(__half2 h) {
    return *reinterpret_cast<uint32_t*>(&h);
}

// ============================================================
// Kernel 0: proj [D][R] fp32 -> projT fp16 [n][k]
// ============================================================
__global__ void k_split_proj(const float* __restrict__ proj) {
    __shared__ float tile[32][33];
    const int k0 = blockIdx.x * 32, n0 = blockIdx.y * 32;
    const int x = threadIdx.x, y = threadIdx.y;
#pragma unroll
    for (int j = 0; j < 32; j += 8)
        tile[y + j][x] = proj[(size_t)(k0 + y + j) * NR + n0 + x];
    __syncthreads();
#pragma unroll
    for (int j = 0; j < 32; j += 8)
        g_pT[(size_t)(n0 + y + j) * ND + k0 + x] = __float2half(tile[x][y + j]);
}

// ============================================================
// Kernel 1: t = batch @ proj  (HMMA fp16, fp32 accum)
// RETILED: 64-row CTAs -> grid 256 (all 148 SMs busy, 2+ CTAs/SM).
// 8 warps as 2(m) x 4(n); warp tile 32x32 = 2x4 mma tiles.
// smem rows padded: stride 144 B -> conflict-free ldmatrix.
// ============================================================
__global__ __launch_bounds__(256, 2) void k_gemm1(const float* __restrict__ batch) {
    __shared__ __align__(16) char smem[64 * 144 + 128 * 144];  // A @0 (9216), B @9216
    const int tid = threadIdx.x, wid = tid >> 5, lane = tid & 31;
    const int warp_m = wid >> 2, warp_n = wid & 3;
    const int row0 = blockIdx.x * 64;

    const uint32_t sA = smem_u32(smem);
    const uint32_t sB = sA + 64 * 144;

    float acc[2][4][4];
#pragma unroll
    for (int mi = 0; mi < 2; mi++)
#pragma unroll
        for (int nj = 0; nj < 4; nj++)
#pragma unroll
            for (int q = 0; q < 4; q++) acc[mi][nj][q] = 0.f;

    uint2 Areg[4];
    uint4 Breg[4];

    auto load_chunk = [&](int c) {
        const int k0 = c * 64;
#pragma unroll
        for (int it = 0; it < 4; it++) {
            int slot = tid + it * 256;
            int r = slot >> 4, q = slot & 15;
            float4 v = *(const float4*)&batch[(size_t)(row0 + r) * ND + k0 + q * 4];
            Areg[it] = make_uint2(h2u(__floats2half2_rn(v.x, v.y)),
                                  h2u(__floats2half2_rn(v.z, v.w)));
        }
#pragma unroll
        for (int it = 0; it < 4; it++) {
            int slot = tid + it * 256;
            int n = slot >> 3, q = slot & 7;
            Breg[it] = *(const uint4*)((const char*)g_pT + (size_t)n * 2048 + (size_t)(k0 + q * 8) * 2);
        }
    };

    load_chunk(0);

    for (int c = 0; c < 16; c++) {
        __syncthreads();  // smem free (prev compute done)
#pragma unroll
        for (int it = 0; it < 4; it++) {
            int slot = tid + it * 256;
            int r = slot >> 4, q = slot & 15;
            *(uint2*)(smem + r * 144 + q * 8) = Areg[it];
        }
#pragma unroll
        for (int it = 0; it < 4; it++) {
            int slot = tid + it * 256;
            int n = slot >> 3, q = slot & 7;
            *(uint4*)(smem + 64 * 144 + n * 144 + q * 16) = Breg[it];
        }
        __syncthreads();
        if (c < 15) load_chunk(c + 1);  // LDGs fly while we do mma below

#pragma unroll
        for (int ks = 0; ks < 4; ks++) {
            uint32_t a[2][4];
#pragma unroll
            for (int mi = 0; mi < 2; mi++) {
                uint32_t addr = sA + (warp_m * 32 + mi * 16 + (lane & 15)) * 144
                              + ks * 32 + (lane >> 4) * 16;
                LDSM4(a[mi][0], a[mi][1], a[mi][2], a[mi][3], addr);
            }
            uint32_t b[4][2];
#pragma unroll
            for (int njp = 0; njp < 2; njp++) {
                uint32_t addr = sB + (warp_n * 32 + njp * 16 + ((lane >> 4) << 3) + (lane & 7)) * 144
                              + ks * 32 + (((lane >> 3) & 1) << 4);
                LDSM4(b[2 * njp][0], b[2 * njp][1], b[2 * njp + 1][0], b[2 * njp + 1][1], addr);
            }
#pragma unroll
            for (int mi = 0; mi < 2; mi++)
#pragma unroll
                for (int nj = 0; nj < 4; nj++)
                    MMA16816(acc[mi][nj], a[mi], b[nj][0], b[nj][1]);
        }
    }

    // Epilogue: fp32 -> fp16, store t-hat
#pragma unroll
    for (int mi = 0; mi < 2; mi++) {
        int r = row0 + warp_m * 32 + mi * 16 + (lane >> 2);
#pragma unroll
        for (int nj = 0; nj < 4; nj++) {
            int col = warp_n * 32 + nj * 8 + (lane & 3) * 2;
            *(uint32_t*)&g_t[(size_t)r * NR + col] =
                h2u(__floats2half2_rn(acc[mi][nj][0], acc[mi][nj][1]));
            *(uint32_t*)&g_t[(size_t)(r + 8) * NR + col] =
                h2u(__floats2half2_rn(acc[mi][nj][2], acc[mi][nj][3]));
        }
    }
}

// ============================================================
// Kernel 2: row norms of t-hat. One warp per row.
// ============================================================
__global__ void k_norms() {
    const int row = blockIdx.x * 8 + (threadIdx.x >> 5);
    const int lane = threadIdx.x & 31;
    uint2 v = *(const uint2*)((const char*)g_t + (size_t)row * 256 + lane * 8);
    __half2 h0 = *reinterpret_cast<__half2*>(&v.x);
    __half2 h1 = *reinterpret_cast<__half2*>(&v.y);
    float2 f0 = __half22float2(h0), f1 = __half22float2(h1);
    float s = f0.x * f0.x + f0.y * f0.y + f1.x * f1.x + f1.y * f1.y;
#pragma unroll
    for (int off = 16; off; off >>= 1) s += __shfl_down_sync(0xffffffffu, s, off);
    if (lane == 0) g_nrm[row] = s;
}

// ============================================================
// Kernel 3: D[b][i][j] = max(n_i + n_j - 2 <t_i, t_j>, 0)
// SYMMETRIC block-pairs bi<=bj (36/batch); mirror via smem transpose.
// (unchanged from R14 pass @ 22.6us)
// ============================================================
#define SMD_STRIDE 132
#define G2_SMEM (2 * 128 * 272)
__global__ __launch_bounds__(256) void k_gemm2(float* __restrict__ out) {
    extern __shared__ __align__(16) char smem[];
    const int tid = threadIdx.x, wid = tid >> 5, lane = tid & 31;
    const int warp_m = wid >> 2, warp_n = wid & 3;
    const int b = blockIdx.y;

    int bi = 0, rem = blockIdx.x;
    while (rem >= 8 - bi) { rem -= 8 - bi; bi++; }
    const int bj = bi + rem;
    const int i0 = bi * 128, j0 = bj * 128;

    const uint32_t sA = smem_u32(smem);
    const uint32_t sB = sA + 128 * 272;

#pragma unroll
    for (int it = 0; it < 8; it++) {
        int slot = tid + it * 256;
        int r = slot >> 4, q = slot & 15;
        *(uint4*)(smem + r * 272 + q * 16) =
            *(const uint4*)((const char*)g_t + (size_t)(b * NS + i0 + r) * 256 + q * 16);
        *(uint4*)(smem + 128 * 272 + r * 272 + q * 16) =
            *(const uint4*)((const char*)g_t + (size_t)(b * NS + j0 + r) * 256 + q * 16);
    }
    __syncthreads();

    float acc[4][4][4];
#pragma unroll
    for (int mi = 0; mi < 4; mi++)
#pragma unroll
        for (int nj = 0; nj < 4; nj++)
#pragma unroll
            for (int q = 0; q < 4; q++) acc[mi][nj][q] = 0.f;

    uint32_t afr[2][4][4], bfr[2][4][2];

#define LOAD_FRAGS(ks, buf)                                                              \
    do {                                                                                 \
        _Pragma("unroll")                                                                \
        for (int mi = 0; mi < 4; mi++) {                                                 \
            uint32_t addr = sA + (warp_m * 64 + mi * 16 + (lane & 15)) * 272             \
                          + (ks) * 32 + (lane >> 4) * 16;                                \
            LDSM4(afr[buf][mi][0], afr[buf][mi][1], afr[buf][mi][2], afr[buf][mi][3], addr); \
        }                                                                                \
        _Pragma("unroll")                                                                \
        for (int njp = 0; njp < 2; njp++) {                                              \
            uint32_t addr = sB + (warp_n * 32 + njp * 16 + ((lane >> 4) << 3) + (lane & 7)) * 272 \
                          + (ks) * 32 + (((lane >> 3) & 1) << 4);                        \
            LDSM4(bfr[buf][2 * njp][0], bfr[buf][2 * njp][1],                            \
                  bfr[buf][2 * njp + 1][0], bfr[buf][2 * njp + 1][1], addr);             \
        }                                                                                \
    } while (0)

    LOAD_FRAGS(0, 0);
#pragma unroll
    for (int ks = 0; ks < 8; ks++) {
        const int cur = ks & 1;
        if (ks < 7) LOAD_FRAGS(ks + 1, cur ^ 1);
#pragma unroll
        for (int mi = 0; mi < 4; mi++)
#pragma unroll
            for (int nj = 0; nj < 4; nj++)
                MMA16816(acc[mi][nj], afr[cur][mi], bfr[cur][nj][0], bfr[cur][nj][1]);
    }
#undef LOAD_FRAGS

    const float* nrm = g_nrm + (size_t)b * NS;
    float oval[4][4][4];
#pragma unroll
    for (int nj = 0; nj < 4; nj++) {
        int j = j0 + warp_n * 32 + nj * 8 + (lane & 3) * 2;
        float njn0 = __ldg(&nrm[j]), njn1 = __ldg(&nrm[j + 1]);
#pragma unroll
        for (int mi = 0; mi < 4; mi++) {
            int i = i0 + warp_m * 64 + mi * 16 + (lane >> 2);
            float ni0 = __ldg(&nrm[i]), ni1 = __ldg(&nrm[i + 8]);
            oval[mi][nj][0] = fmaxf(ni0 + njn0 - 2.f * acc[mi][nj][0], 0.f);
            oval[mi][nj][1] = fmaxf(ni0 + njn1 - 2.f * acc[mi][nj][1], 0.f);
            oval[mi][nj][2] = fmaxf(ni1 + njn0 - 2.f * acc[mi][nj][2], 0.f);
            oval[mi][nj][3] = fmaxf(ni1 + njn1 - 2.f * acc[mi][nj][3], 0.f);
            *(float2*)&out[((size_t)b * NS + i) * NS + j] = make_float2(oval[mi][nj][0], oval[mi][nj][1]);
            *(float2*)&out[((size_t)b * NS + i + 8) * NS + j] = make_float2(oval[mi][nj][2], oval[mi][nj][3]);
        }
    }

    if (bi != bj) {
        __syncthreads();
        float* smD = (float*)smem;
#pragma unroll
        for (int nj = 0; nj < 4; nj++) {
            int jl = warp_n * 32 + nj * 8 + (lane & 3) * 2;
#pragma unroll
            for (int mi = 0; mi < 4; mi++) {
                int il = warp_m * 64 + mi * 16 + (lane >> 2);
                smD[(size_t)jl * SMD_STRIDE + il]            = oval[mi][nj][0];
                smD[(size_t)(jl + 1) * SMD_STRIDE + il]      = oval[mi][nj][1];
                smD[(size_t)jl * SMD_STRIDE + il + 8]        = oval[mi][nj][2];
                smD[(size_t)(jl + 1) * SMD_STRIDE + il + 8]  = oval[mi][nj][3];
            }
        }
        __syncthreads();
#pragma unroll
        for (int it = 0; it < 16; it++) {
            int slot = tid + it * 256;
            int cg = slot & 31, jr = slot >> 5;
            float4 v = *(const float4*)&smD[(size_t)jr * SMD_STRIDE + cg * 4];
            *(float4*)&out[((size_t)b * NS + j0 + jr) * NS + i0 + cg * 4] = v;
        }
    }
}

// ============================================================
extern "C" void kernel_launch(void* const* d_in, const int* in_sizes, int n_in,
                              void* d_out, int out_size) {
    (void)in_sizes; (void)n_in; (void)out_size;
    const float* batch = (const float*)d_in[0];  // [16,1024,1024]
    const float* proj  = (const float*)d_in[1];  // [1024,128]
    float* out = (float*)d_out;                  // [16,1024,1024]

    cudaFuncSetAttribute(k_gemm2, cudaFuncAttributeMaxDynamicSharedMemorySize, G2_SMEM);

    k_split_proj<<<dim3(32, 4), dim3(32, 8)>>>(proj);
    k_gemm1<<<(NB * NS) / 64, 256>>>(batch);
    k_norms<<<(NB * NS) / 8, 256>>>();
    k_gemm2<<<dim3(36, NB), 256, G2_SMEM>>>(out);
}